// round 1
// baseline (speedup 1.0000x reference)
#include <cuda_runtime.h>
#include <cstdint>

// ---------------------------------------------------------------------------
// StateTransitionModel (2-layer Mamba): fp32 pipeline
//   per layer: in_proj GEMM -> conv+silu -> x_proj -> dt_proj+softplus ->
//              fused selective scan (+gate silu) -> out_proj GEMM
// ---------------------------------------------------------------------------

#define LOG2E 1.4426950408889634f

static const int BATCH   = 2;
static const int SEQ     = 4096;
static const int ROWS    = BATCH * SEQ;   // 8192
static const int DMODEL  = 256;
static const int DINNER  = 512;
static const int DSTATE  = 16;
static const int DTRANK  = 16;
static const int XDBL_N  = DTRANK + 2 * DSTATE; // 48

// scratch (device globals; no runtime allocation allowed)
__device__ float g_xz  [ROWS * 2 * DINNER];  // in_proj out: x | gate
__device__ float g_xs  [ROWS * DINNER];      // conv+silu out
__device__ float g_xdbl[ROWS * XDBL_N];      // x_proj out
__device__ float g_dt  [ROWS * DINNER];      // softplus(dt_proj)
__device__ float g_yg  [ROWS * DINNER];      // scan out * silu(gate)
__device__ float g_z   [ROWS * DMODEL];      // inter-layer activation

// ---------------------------------------------------------------- intrinsics
__device__ __forceinline__ float ex2f(float x) {
    float y; asm("ex2.approx.f32 %0, %1;" : "=f"(y) : "f"(x)); return y;
}
__device__ __forceinline__ float rcpf(float x) {
    float y; asm("rcp.approx.f32 %0, %1;" : "=f"(y) : "f"(x)); return y;
}
__device__ __forceinline__ unsigned long long pack2(float a, float b) {
    unsigned long long r;
    asm("mov.b64 %0, {%1, %2};" : "=l"(r)
        : "r"(__float_as_uint(a)), "r"(__float_as_uint(b)));
    return r;
}
__device__ __forceinline__ void fma2(unsigned long long& acc,
                                     unsigned long long a, unsigned long long b) {
    asm("fma.rn.f32x2 %0, %1, %2, %0;" : "+l"(acc) : "l"(a), "l"(b));
}
__device__ __forceinline__ float2 unpack2(unsigned long long v) {
    unsigned lo, hi;
    asm("mov.b64 {%0, %1}, %2;" : "=r"(lo), "=r"(hi) : "l"(v));
    return make_float2(__uint_as_float(lo), __uint_as_float(hi));
}
__device__ __forceinline__ void cp16(void* dst, const void* src) {
    unsigned d = (unsigned)__cvta_generic_to_shared(dst);
    asm volatile("cp.async.ca.shared.global [%0], [%1], 16;" :: "r"(d), "l"(src));
}

// --------------------------------------------------------------- SGEMM (NT)
// C[M,N] = A[M,K] @ W[N,K]^T  (both K-contiguous). 128x128x8 tile, 256 thr,
// 8x8 micro-tile, inner loop in packed fp32x2 FFMA2 (2x fp32 rate on B300).
__global__ void __launch_bounds__(256) sgemm_nt(
    const float* __restrict__ A, const float* __restrict__ W,
    float* __restrict__ C, int N, int K)
{
    __shared__ float As[8][132];
    __shared__ float Ws[8][132];
    const int tid = threadIdx.x;
    const int bm = blockIdx.y << 7;
    const int bn = blockIdx.x << 7;
    const int lrow = tid >> 1;
    const int lk = (tid & 1) << 2;
    const float* Ag = A + (size_t)(bm + lrow) * K + lk;
    const float* Wg = W + (size_t)(bn + lrow) * K + lk;
    const int tx = tid & 15, ty = tid >> 4;

    unsigned long long acc[8][4];
#pragma unroll
    for (int i = 0; i < 8; i++)
#pragma unroll
        for (int j = 0; j < 4; j++) acc[i][j] = 0ull;

    for (int k0 = 0; k0 < K; k0 += 8) {
        float4 av = *(const float4*)(Ag + k0);
        float4 wv = *(const float4*)(Wg + k0);
        __syncthreads();
        As[lk + 0][lrow] = av.x; As[lk + 1][lrow] = av.y;
        As[lk + 2][lrow] = av.z; As[lk + 3][lrow] = av.w;
        Ws[lk + 0][lrow] = wv.x; Ws[lk + 1][lrow] = wv.y;
        Ws[lk + 2][lrow] = wv.z; Ws[lk + 3][lrow] = wv.w;
        __syncthreads();
#pragma unroll
        for (int k = 0; k < 8; k++) {
            float4 a0 = *(const float4*)&As[k][(ty << 3)];
            float4 a1 = *(const float4*)&As[k][(ty << 3) + 4];
            ulonglong2 b0 = *(const ulonglong2*)&Ws[k][(tx << 3)];
            ulonglong2 b1 = *(const ulonglong2*)&Ws[k][(tx << 3) + 4];
            float aa[8] = {a0.x, a0.y, a0.z, a0.w, a1.x, a1.y, a1.z, a1.w};
#pragma unroll
            for (int i = 0; i < 8; i++) {
                unsigned long long ad = pack2(aa[i], aa[i]);
                fma2(acc[i][0], ad, b0.x);
                fma2(acc[i][1], ad, b0.y);
                fma2(acc[i][2], ad, b1.x);
                fma2(acc[i][3], ad, b1.y);
            }
        }
    }
#pragma unroll
    for (int i = 0; i < 8; i++) {
        int row = bm + (ty << 3) + i;
        float2 c0 = unpack2(acc[i][0]), c1 = unpack2(acc[i][1]);
        float2 c2 = unpack2(acc[i][2]), c3 = unpack2(acc[i][3]);
        *(float4*)&C[(size_t)row * N + bn + (tx << 3)]     = make_float4(c0.x, c0.y, c1.x, c1.y);
        *(float4*)&C[(size_t)row * N + bn + (tx << 3) + 4] = make_float4(c2.x, c2.y, c3.x, c3.y);
    }
}

// ---------------------------------------------------- causal depthwise conv
__global__ void __launch_bounds__(256) conv_silu_k(
    const float* __restrict__ cw, const float* __restrict__ cb)
{
    int idx = blockIdx.x * 256 + threadIdx.x;   // ROWS*DINNER exact
    int d = idx & (DINNER - 1);
    int row = idx >> 9;
    int t = row & (SEQ - 1);
    float4 w = *(const float4*)(cw + (d << 2));
    float acc = cb[d];
    if (t >= 3) acc += g_xz[(size_t)(row - 3) * 1024 + d] * w.x;
    if (t >= 2) acc += g_xz[(size_t)(row - 2) * 1024 + d] * w.y;
    if (t >= 1) acc += g_xz[(size_t)(row - 1) * 1024 + d] * w.z;
    acc += g_xz[(size_t)row * 1024 + d] * w.w;
    g_xs[idx] = acc * rcpf(1.f + ex2f(-acc * LOG2E));   // silu
}

// ----------------------------------------------------------- x_proj (N=48)
// block: 64 rows x 48 cols, 192 threads, K staged in 64-chunks via smem
__global__ void __launch_bounds__(192) xproj_k(const float* __restrict__ xpw)
{
    __shared__ float xs[64 * 65];
    __shared__ float ws[48 * 65];
    const int tid = threadIdx.x;
    const int row0 = blockIdx.x << 6;
    const int rg = tid / 12, ng = tid % 12;
    float acc[4][4] = {};
    for (int kc = 0; kc < DINNER; kc += 64) {
        __syncthreads();
        for (int idx = tid; idx < 64 * 64; idx += 192) {
            int r = idx >> 6, k = idx & 63;
            xs[r * 65 + k] = g_xs[(size_t)(row0 + r) * DINNER + kc + k];
        }
        for (int idx = tid; idx < 48 * 64; idx += 192) {
            int n = idx >> 6, k = idx & 63;
            ws[n * 65 + k] = xpw[n * DINNER + kc + k];
        }
        __syncthreads();
#pragma unroll 4
        for (int k = 0; k < 64; k++) {
            float x0 = xs[(rg * 4 + 0) * 65 + k];
            float x1 = xs[(rg * 4 + 1) * 65 + k];
            float x2 = xs[(rg * 4 + 2) * 65 + k];
            float x3 = xs[(rg * 4 + 3) * 65 + k];
            float w0 = ws[(ng * 4 + 0) * 65 + k];
            float w1 = ws[(ng * 4 + 1) * 65 + k];
            float w2 = ws[(ng * 4 + 2) * 65 + k];
            float w3 = ws[(ng * 4 + 3) * 65 + k];
            acc[0][0] += x0 * w0; acc[0][1] += x0 * w1; acc[0][2] += x0 * w2; acc[0][3] += x0 * w3;
            acc[1][0] += x1 * w0; acc[1][1] += x1 * w1; acc[1][2] += x1 * w2; acc[1][3] += x1 * w3;
            acc[2][0] += x2 * w0; acc[2][1] += x2 * w1; acc[2][2] += x2 * w2; acc[2][3] += x2 * w3;
            acc[3][0] += x3 * w0; acc[3][1] += x3 * w1; acc[3][2] += x3 * w2; acc[3][3] += x3 * w3;
        }
    }
#pragma unroll
    for (int i = 0; i < 4; i++)
#pragma unroll
        for (int j = 0; j < 4; j++)
            g_xdbl[(size_t)(row0 + rg * 4 + i) * XDBL_N + ng * 4 + j] = acc[i][j];
}

// ------------------------------------------------- dt_proj + softplus (K=16)
__global__ void __launch_bounds__(512) dtproj_k(
    const float* __restrict__ dtw, const float* __restrict__ dtb)
{
    __shared__ float ws[512 * 17];
    __shared__ float din[16][16];
    const int tid = threadIdx.x;
    const int row0 = blockIdx.x << 4;
    for (int idx = tid; idx < 512 * 16; idx += 512)
        ws[(idx >> 4) * 17 + (idx & 15)] = dtw[idx];
    if (tid < 256)
        din[tid >> 4][tid & 15] = g_xdbl[(size_t)(row0 + (tid >> 4)) * XDBL_N + (tid & 15)];
    __syncthreads();
    float bias = dtb[tid];
#pragma unroll 4
    for (int r = 0; r < 16; r++) {
        float acc = bias;
#pragma unroll
        for (int k = 0; k < 16; k++) acc += din[r][k] * ws[tid * 17 + k];
        float sp = (acc > 20.f) ? acc : log1pf(__expf(acc));
        g_dt[(size_t)(row0 + r) * DINNER + tid] = sp;
    }
}

// -------------------------------------------------------- selective scan
// 256 blocks x 64 threads. Block owns (b, 4 d-channels); 16 lanes per d (lane=n).
// h kept in a register; operands staged in smem via cp.async (64-step chunks,
// double-buffered). y reduced across 16 lanes with shfl; fused +x*D and
// *silu(gate) epilogue.
#define SCHUNK 64
__global__ void __launch_bounds__(64) scan_k(
    const float* __restrict__ A_log, const float* __restrict__ Dpar)
{
    __shared__ float s_dt[2][SCHUNK][4];
    __shared__ float s_x [2][SCHUNK][4];
    __shared__ float s_g [2][SCHUNK][4];
    __shared__ float s_bc[2][SCHUNK][32];

    const int tid = threadIdx.x;
    const int bid = blockIdx.x;
    const int b = bid >> 7;
    const int d0 = (bid & 127) << 2;
    const int p = tid >> 4, n = tid & 15;
    const int d = d0 + p;

    const float A2 = -__expf(A_log[d * DSTATE + n]) * LOG2E;
    const float Dp = Dpar[d];
    float h = 0.f;
    const long rowbase = (long)b * SEQ;

    auto load = [&](int c, int buf) {
        long tb = rowbase + (long)c * SCHUNK;
        {   // dt / x / gate tiles: one 16B (4-float d-row) per t per thread
            cp16(&s_dt[buf][tid][0], &g_dt[(tb + tid) * DINNER + d0]);
            cp16(&s_x [buf][tid][0], &g_xs[(tb + tid) * DINNER + d0]);
            cp16(&s_g [buf][tid][0], &g_xz[(tb + tid) * 1024 + DINNER + d0]);
        }
#pragma unroll
        for (int j = 0; j < 8; j++) {           // B|C: 32 floats per t
            int idx = tid + 64 * j;             // 0..511
            int t = idx >> 3, q = (idx & 7) << 2;
            cp16(&s_bc[buf][t][q], &g_xdbl[(tb + t) * XDBL_N + DTRANK + q]);
        }
    };

    load(0, 0); asm volatile("cp.async.commit_group;");
    load(1, 1); asm volatile("cp.async.commit_group;");

    for (int c = 0; c < SEQ / SCHUNK; c++) {
        const int buf = c & 1;
        asm volatile("cp.async.wait_group 1;");
        __syncthreads();
        const long outb = rowbase + (long)c * SCHUNK;
#pragma unroll 8
        for (int i = 0; i < SCHUNK; i++) {
            float dtv = s_dt[buf][i][p];
            float xv  = s_x [buf][i][p];
            float Bv  = s_bc[buf][i][n];
            float Cv  = s_bc[buf][i][16 + n];
            float a = ex2f(dtv * A2);                 // exp(dt*A)
            h = a * h + (dtv * xv) * Bv;              // h = dA*h + dt*B*x
            float r = h * Cv;
            r += __shfl_xor_sync(0xffffffffu, r, 8);
            r += __shfl_xor_sync(0xffffffffu, r, 4);
            r += __shfl_xor_sync(0xffffffffu, r, 2);
            r += __shfl_xor_sync(0xffffffffu, r, 1);
            float g = s_g[buf][i][p];
            float sig = g * rcpf(1.f + ex2f(-g * LOG2E));   // silu(gate)
            float y = (r + xv * Dp) * sig;
            if (n == 0) g_yg[(outb + i) * DINNER + d] = y;
        }
        __syncthreads();
        if (c + 2 < SEQ / SCHUNK) load(c + 2, buf);
        asm volatile("cp.async.commit_group;");
    }
}

// ------------------------------------------------------------------- launch
extern "C" void kernel_launch(void* const* d_in, const int* in_sizes, int n_in,
                              void* d_out, int out_size)
{
    const float* z      = (const float*)d_in[0];
    const float* in_w   = (const float*)d_in[1];
    const float* conv_w = (const float*)d_in[2];
    const float* conv_b = (const float*)d_in[3];
    const float* xp_w   = (const float*)d_in[4];
    const float* dt_w   = (const float*)d_in[5];
    const float* dt_b   = (const float*)d_in[6];
    const float* A_log  = (const float*)d_in[7];
    const float* D_par  = (const float*)d_in[8];
    const float* out_w  = (const float*)d_in[9];

    float *xz, *yg, *zb;
    cudaGetSymbolAddress((void**)&xz, g_xz);
    cudaGetSymbolAddress((void**)&yg, g_yg);
    cudaGetSymbolAddress((void**)&zb, g_z);

    const float* zin = z;
    for (int l = 0; l < 2; l++) {
        float* zout = (l == 0) ? zb : (float*)d_out;
        // in_proj: [8192,256] @ [1024,256]^T -> [8192,1024]
        sgemm_nt<<<dim3(1024 / 128, ROWS / 128), 256>>>(
            zin, in_w + (size_t)l * 1024 * DMODEL, xz, 1024, DMODEL);
        conv_silu_k<<<(ROWS * DINNER) / 256, 256>>>(
            conv_w + (size_t)l * DINNER * 4, conv_b + (size_t)l * DINNER);
        xproj_k<<<ROWS / 64, 192>>>(xp_w + (size_t)l * XDBL_N * DINNER);
        dtproj_k<<<ROWS / 16, 512>>>(
            dt_w + (size_t)l * DINNER * DTRANK, dt_b + (size_t)l * DINNER);
        scan_k<<<256, 64>>>(
            A_log + (size_t)l * DINNER * DSTATE, D_par + (size_t)l * DINNER);
        // out_proj: [8192,512] @ [256,512]^T -> [8192,256]
        sgemm_nt<<<dim3(DMODEL / 128, ROWS / 128), 256>>>(
            yg, out_w + (size_t)l * DMODEL * DINNER, zout, DMODEL, DINNER);
        zin = zout;
    }
}

// round 3
// speedup vs baseline: 1.3311x; 1.3311x over previous
#include <cuda_runtime.h>
#include <cstdint>

// ---------------------------------------------------------------------------
// StateTransitionModel (2-layer Mamba), round 3:
//   mma.sync tf32 GEMMs (arch-portable HMMA path; tcgen05 is blocked by the
//   harness's compute_103 virtual arch) + chunked parallel selective scan.
// ---------------------------------------------------------------------------

#define LOG2E 1.4426950408889634f

static const int BATCH   = 2;
static const int SEQ     = 4096;
static const int ROWS    = BATCH * SEQ;   // 8192
static const int DMODEL  = 256;
static const int DINNER  = 512;
static const int DSTATE  = 16;
static const int DTRANK  = 16;
static const int XDBL_N  = DTRANK + 2 * DSTATE; // 48
static const int PCHUNK  = 8;                   // scan chunks per sequence
static const int CLEN    = SEQ / PCHUNK;        // 512

// scratch (device globals; no runtime allocation allowed)
__device__ float g_xz  [ROWS * 2 * DINNER];  // in_proj out: x | gate
__device__ float g_xs  [ROWS * DINNER];      // conv+silu out
__device__ float g_gs  [ROWS * DINNER];      // silu(gate)
__device__ float g_xdbl[ROWS * XDBL_N];      // x_proj out
__device__ float g_dt  [ROWS * DINNER];      // softplus(dt_proj)
__device__ float g_yg  [ROWS * DINNER];      // scan out * silu(gate)
__device__ float g_z   [ROWS * DMODEL];      // inter-layer activation
__device__ float g_hf  [BATCH * PCHUNK * DINNER * DSTATE]; // chunk local finals
__device__ float g_dec [BATCH * PCHUNK * DINNER * DSTATE]; // chunk decay
__device__ float g_hi  [BATCH * PCHUNK * DINNER * DSTATE]; // corrected initials

// ---------------------------------------------------------------- intrinsics
__device__ __forceinline__ float ex2f(float x) {
    float y; asm("ex2.approx.f32 %0, %1;" : "=f"(y) : "f"(x)); return y;
}
__device__ __forceinline__ float rcpf(float x) {
    float y; asm("rcp.approx.f32 %0, %1;" : "=f"(y) : "f"(x)); return y;
}
__device__ __forceinline__ uint32_t tf32r(float x) {
    uint32_t r; asm("cvt.rna.tf32.f32 %0, %1;" : "=r"(r) : "f"(x)); return r;
}
__device__ __forceinline__ void cp16(void* dst, const void* src) {
    unsigned d = (unsigned)__cvta_generic_to_shared(dst);
    asm volatile("cp.async.ca.shared.global [%0], [%1], 16;" :: "r"(d), "l"(src));
}
__device__ __forceinline__ void mma_tf32(float* c, const uint32_t* a,
                                         const uint32_t* b) {
    asm volatile(
        "mma.sync.aligned.m16n8k8.row.col.f32.tf32.tf32.f32 "
        "{%0,%1,%2,%3}, {%4,%5,%6,%7}, {%8,%9}, {%0,%1,%2,%3};"
        : "+f"(c[0]), "+f"(c[1]), "+f"(c[2]), "+f"(c[3])
        : "r"(a[0]), "r"(a[1]), "r"(a[2]), "r"(a[3]), "r"(b[0]), "r"(b[1]));
}

// ------------------------------------------------------------ tf32 GEMM (NT)
// C[M,N] = A[M,K] @ W[N,K]^T, fp32 in/out, m16n8k8 tf32 mma.sync.
// CTA tile 128x128, 8 warps (2x4), warp tile 64x32, K-chunk 32,
// register-staged double-buffered SMEM, cvt.rna.tf32 at the STS stage.
static const int GPAD = 36;                         // 32 + 4 pad (floats)
static const int GEMM_SMEM = 4 * 128 * GPAD * 4;    // 73728 B

__global__ void __launch_bounds__(256) gemm_tc(
    const float* __restrict__ A, const float* __restrict__ W,
    float* __restrict__ C, int N, int K)
{
    extern __shared__ float sm[];
    float* Abuf[2] = { sm,                sm + 128 * GPAD };
    float* Wbuf[2] = { sm + 2*128*GPAD,   sm + 3*128*GPAD };

    const int tid  = threadIdx.x;
    const int bm   = blockIdx.y << 7;
    const int bn   = blockIdx.x << 7;
    const int warp = tid >> 5, lane = tid & 31;
    const int wm   = warp >> 2, wn = warp & 3;      // 2 x 4 warp grid
    const int gid  = lane >> 2, tig = lane & 3;

    float acc[4][4][4];
#pragma unroll
    for (int i = 0; i < 4; i++)
#pragma unroll
        for (int j = 0; j < 4; j++)
#pragma unroll
            for (int q = 0; q < 4; q++) acc[i][j][q] = 0.f;

    uint4 ra[4], rw[4];

    auto ldg = [&](int c) {
        const int kc = c << 5;
#pragma unroll
        for (int r = 0; r < 4; r++) {
            int idx = tid + (r << 8);
            int row = idx >> 3, q = (idx & 7) << 2;
            float4 va = *(const float4*)(A + (size_t)(bm + row) * K + kc + q);
            float4 vw = *(const float4*)(W + (size_t)(bn + row) * K + kc + q);
            ra[r] = make_uint4(tf32r(va.x), tf32r(va.y), tf32r(va.z), tf32r(va.w));
            rw[r] = make_uint4(tf32r(vw.x), tf32r(vw.y), tf32r(vw.z), tf32r(vw.w));
        }
    };
    auto sts = [&](int buf) {
#pragma unroll
        for (int r = 0; r < 4; r++) {
            int idx = tid + (r << 8);
            int row = idx >> 3, q = (idx & 7) << 2;
            *(uint4*)(Abuf[buf] + row * GPAD + q) = ra[r];
            *(uint4*)(Wbuf[buf] + row * GPAD + q) = rw[r];
        }
    };
    auto compute = [&](int buf) {
        const uint32_t* Au = (const uint32_t*)Abuf[buf];
        const uint32_t* Wu = (const uint32_t*)Wbuf[buf];
#pragma unroll
        for (int kk = 0; kk < 4; kk++) {
            const int k0 = (kk << 3) + tig;
            uint32_t af[4][4], bf[4][2];
#pragma unroll
            for (int mi = 0; mi < 4; mi++) {
                int m = (wm << 6) + (mi << 4) + gid;
                af[mi][0] = Au[m * GPAD + k0];
                af[mi][1] = Au[(m + 8) * GPAD + k0];
                af[mi][2] = Au[m * GPAD + k0 + 4];
                af[mi][3] = Au[(m + 8) * GPAD + k0 + 4];
            }
#pragma unroll
            for (int nj = 0; nj < 4; nj++) {
                int n = (wn << 5) + (nj << 3) + gid;
                bf[nj][0] = Wu[n * GPAD + k0];
                bf[nj][1] = Wu[n * GPAD + k0 + 4];
            }
#pragma unroll
            for (int mi = 0; mi < 4; mi++)
#pragma unroll
                for (int nj = 0; nj < 4; nj++)
                    mma_tf32(acc[mi][nj], af[mi], bf[nj]);
        }
    };

    const int NC = K >> 5;
    ldg(0); sts(0); __syncthreads();
    for (int c = 0; c < NC; c++) {
        if (c + 1 < NC) ldg(c + 1);
        compute(c & 1);
        if (c + 1 < NC) { sts((c + 1) & 1); __syncthreads(); }
    }

#pragma unroll
    for (int mi = 0; mi < 4; mi++) {
#pragma unroll
        for (int nj = 0; nj < 4; nj++) {
            int row = bm + (wm << 6) + (mi << 4) + gid;
            int col = bn + (wn << 5) + (nj << 3) + (tig << 1);
            *(float2*)(C + (size_t)row * N + col) =
                make_float2(acc[mi][nj][0], acc[mi][nj][1]);
            *(float2*)(C + (size_t)(row + 8) * N + col) =
                make_float2(acc[mi][nj][2], acc[mi][nj][3]);
        }
    }
}

// --------------------------------------- causal depthwise conv + both silus
__global__ void __launch_bounds__(256) conv_silu_k(
    const float* __restrict__ cw, const float* __restrict__ cb)
{
    int idx = blockIdx.x * 256 + threadIdx.x;   // ROWS*DINNER exact
    int d = idx & (DINNER - 1);
    int row = idx >> 9;
    int t = row & (SEQ - 1);
    float4 w = *(const float4*)(cw + (d << 2));
    float acc = cb[d];
    if (t >= 3) acc += g_xz[(size_t)(row - 3) * 1024 + d] * w.x;
    if (t >= 2) acc += g_xz[(size_t)(row - 2) * 1024 + d] * w.y;
    if (t >= 1) acc += g_xz[(size_t)(row - 1) * 1024 + d] * w.z;
    acc += g_xz[(size_t)row * 1024 + d] * w.w;
    g_xs[idx] = acc * rcpf(1.f + ex2f(-acc * LOG2E));            // silu(conv)
    float g = g_xz[(size_t)row * 1024 + DINNER + d];
    g_gs[idx] = g * rcpf(1.f + ex2f(-g * LOG2E));                // silu(gate)
}

// ----------------------------------------------------------- x_proj (N=48)
__global__ void __launch_bounds__(192) xproj_k(const float* __restrict__ xpw)
{
    __shared__ float xs[64 * 65];
    __shared__ float ws[48 * 65];
    const int tid = threadIdx.x;
    const int row0 = blockIdx.x << 6;
    const int rg = tid / 12, ng = tid % 12;
    float acc[4][4] = {};
    for (int kc = 0; kc < DINNER; kc += 64) {
        __syncthreads();
        for (int idx = tid; idx < 64 * 64; idx += 192) {
            int r = idx >> 6, k = idx & 63;
            xs[r * 65 + k] = g_xs[(size_t)(row0 + r) * DINNER + kc + k];
        }
        for (int idx = tid; idx < 48 * 64; idx += 192) {
            int n = idx >> 6, k = idx & 63;
            ws[n * 65 + k] = xpw[n * DINNER + kc + k];
        }
        __syncthreads();
#pragma unroll 4
        for (int k = 0; k < 64; k++) {
            float x0 = xs[(rg * 4 + 0) * 65 + k];
            float x1 = xs[(rg * 4 + 1) * 65 + k];
            float x2 = xs[(rg * 4 + 2) * 65 + k];
            float x3 = xs[(rg * 4 + 3) * 65 + k];
            float w0 = ws[(ng * 4 + 0) * 65 + k];
            float w1 = ws[(ng * 4 + 1) * 65 + k];
            float w2 = ws[(ng * 4 + 2) * 65 + k];
            float w3 = ws[(ng * 4 + 3) * 65 + k];
            acc[0][0] += x0 * w0; acc[0][1] += x0 * w1; acc[0][2] += x0 * w2; acc[0][3] += x0 * w3;
            acc[1][0] += x1 * w0; acc[1][1] += x1 * w1; acc[1][2] += x1 * w2; acc[1][3] += x1 * w3;
            acc[2][0] += x2 * w0; acc[2][1] += x2 * w1; acc[2][2] += x2 * w2; acc[2][3] += x2 * w3;
            acc[3][0] += x3 * w0; acc[3][1] += x3 * w1; acc[3][2] += x3 * w2; acc[3][3] += x3 * w3;
        }
    }
#pragma unroll
    for (int i = 0; i < 4; i++)
#pragma unroll
        for (int j = 0; j < 4; j++)
            g_xdbl[(size_t)(row0 + rg * 4 + i) * XDBL_N + ng * 4 + j] = acc[i][j];
}

// ------------------------------------------------- dt_proj + softplus (K=16)
__global__ void __launch_bounds__(512) dtproj_k(
    const float* __restrict__ dtw, const float* __restrict__ dtb)
{
    __shared__ float ws[512 * 17];
    __shared__ float din[16][16];
    const int tid = threadIdx.x;
    const int row0 = blockIdx.x << 4;
    for (int idx = tid; idx < 512 * 16; idx += 512)
        ws[(idx >> 4) * 17 + (idx & 15)] = dtw[idx];
    if (tid < 256)
        din[tid >> 4][tid & 15] = g_xdbl[(size_t)(row0 + (tid >> 4)) * XDBL_N + (tid & 15)];
    __syncthreads();
    float bias = dtb[tid];
#pragma unroll 4
    for (int r = 0; r < 16; r++) {
        float acc = bias;
#pragma unroll
        for (int k = 0; k < 16; k++) acc += din[r][k] * ws[tid * 17 + k];
        float sp = (acc > 20.f) ? acc : log1pf(__expf(acc));
        g_dt[(size_t)(row0 + r) * DINNER + tid] = sp;
    }
}

// ------------------------------------------------ scan pass1: local chunks
// grid (PCHUNK, DINNER/4, BATCH), 64 thr. Block = 4 d-channels of one chunk.
#define SCHUNK 64
__global__ void __launch_bounds__(64) scan_pass1(const float* __restrict__ A_log)
{
    __shared__ float s_dt[2][SCHUNK][4];
    __shared__ float s_x [2][SCHUNK][4];
    __shared__ float s_b [2][SCHUNK][16];

    const int tid = threadIdx.x;
    const int chunk = blockIdx.x, dblk = blockIdx.y, b = blockIdx.z;
    const int d0 = dblk << 2;
    const int p = tid >> 4, n = tid & 15;
    const int d = d0 + p;

    const float A2 = -__expf(A_log[d * DSTATE + n]) * LOG2E;
    float h = 0.f, sumdt = 0.f;
    const long base = (long)b * SEQ + (long)chunk * CLEN;

    auto load = [&](int cc, int buf) {
        long tb = base + (long)cc * SCHUNK;
        cp16(&s_dt[buf][tid][0], &g_dt[(tb + tid) * DINNER + d0]);
        cp16(&s_x [buf][tid][0], &g_xs[(tb + tid) * DINNER + d0]);
#pragma unroll
        for (int j = 0; j < 4; j++) {
            int idx = tid + 64 * j;
            int t = idx >> 2, q = (idx & 3) << 2;
            cp16(&s_b[buf][t][q], &g_xdbl[(tb + t) * XDBL_N + DTRANK + q]);
        }
    };

    load(0, 0); asm volatile("cp.async.commit_group;");
    load(1, 1); asm volatile("cp.async.commit_group;");

    for (int cc = 0; cc < CLEN / SCHUNK; cc++) {
        const int buf = cc & 1;
        asm volatile("cp.async.wait_group 1;");
        __syncthreads();
#pragma unroll 8
        for (int i = 0; i < SCHUNK; i++) {
            float dtv = s_dt[buf][i][p];
            float xv  = s_x [buf][i][p];
            float Bv  = s_b [buf][i][n];
            h = ex2f(dtv * A2) * h + (dtv * xv) * Bv;
            sumdt += dtv;
        }
        __syncthreads();
        if (cc + 2 < CLEN / SCHUNK) load(cc + 2, buf);
        asm volatile("cp.async.commit_group;");
    }
    int o = ((b * PCHUNK + chunk) * DINNER + d) * DSTATE + n;
    g_hf [o] = h;
    g_dec[o] = ex2f(A2 * sumdt);
}

// --------------------------------------- scan fixup: sequential over chunks
__global__ void __launch_bounds__(256) scan_fixup()
{
    int idx = blockIdx.x * 256 + threadIdx.x;    // BATCH*DINNER*DSTATE = 16384
    int b = idx >> 13;
    int dn = idx & 8191;
    float h = 0.f;
#pragma unroll
    for (int c = 0; c < PCHUNK; c++) {
        int o = ((b * PCHUNK + c) << 13) + dn;
        g_hi[o] = h;
        h = g_hf[o] + g_dec[o] * h;
    }
}

// -------------------------------- scan pass2: corrected scan + y + gate mul
__global__ void __launch_bounds__(64) scan_pass2(
    const float* __restrict__ A_log, const float* __restrict__ Dpar)
{
    __shared__ float s_dt[2][SCHUNK][4];
    __shared__ float s_x [2][SCHUNK][4];
    __shared__ float s_g [2][SCHUNK][4];
    __shared__ float s_bc[2][SCHUNK][32];

    const int tid = threadIdx.x;
    const int chunk = blockIdx.x, dblk = blockIdx.y, b = blockIdx.z;
    const int d0 = dblk << 2;
    const int p = tid >> 4, n = tid & 15;
    const int d = d0 + p;

    const float A2 = -__expf(A_log[d * DSTATE + n]) * LOG2E;
    const float Dp = Dpar[d];
    float h = g_hi[((b * PCHUNK + chunk) * DINNER + d) * DSTATE + n];
    const long base = (long)b * SEQ + (long)chunk * CLEN;

    auto load = [&](int cc, int buf) {
        long tb = base + (long)cc * SCHUNK;
        cp16(&s_dt[buf][tid][0], &g_dt[(tb + tid) * DINNER + d0]);
        cp16(&s_x [buf][tid][0], &g_xs[(tb + tid) * DINNER + d0]);
        cp16(&s_g [buf][tid][0], &g_gs[(tb + tid) * DINNER + d0]);
#pragma unroll
        for (int j = 0; j < 8; j++) {
            int idx = tid + 64 * j;
            int t = idx >> 3, q = (idx & 7) << 2;
            cp16(&s_bc[buf][t][q], &g_xdbl[(tb + t) * XDBL_N + DTRANK + q]);
        }
    };

    load(0, 0); asm volatile("cp.async.commit_group;");
    load(1, 1); asm volatile("cp.async.commit_group;");

    for (int cc = 0; cc < CLEN / SCHUNK; cc++) {
        const int buf = cc & 1;
        asm volatile("cp.async.wait_group 1;");
        __syncthreads();
        const long outb = base + (long)cc * SCHUNK;
#pragma unroll 8
        for (int i = 0; i < SCHUNK; i++) {
            float dtv = s_dt[buf][i][p];
            float xv  = s_x [buf][i][p];
            float Bv  = s_bc[buf][i][n];
            float Cv  = s_bc[buf][i][16 + n];
            h = ex2f(dtv * A2) * h + (dtv * xv) * Bv;
            float r = h * Cv;
            r += __shfl_xor_sync(0xffffffffu, r, 8);
            r += __shfl_xor_sync(0xffffffffu, r, 4);
            r += __shfl_xor_sync(0xffffffffu, r, 2);
            r += __shfl_xor_sync(0xffffffffu, r, 1);
            if (n == 0) {
                float y = (r + xv * Dp) * s_g[buf][i][p];
                g_yg[(outb + i) * DINNER + d] = y;
            }
        }
        __syncthreads();
        if (cc + 2 < CLEN / SCHUNK) load(cc + 2, buf);
        asm volatile("cp.async.commit_group;");
    }
}

// ------------------------------------------------------------------- launch
extern "C" void kernel_launch(void* const* d_in, const int* in_sizes, int n_in,
                              void* d_out, int out_size)
{
    const float* z      = (const float*)d_in[0];
    const float* in_w   = (const float*)d_in[1];
    const float* conv_w = (const float*)d_in[2];
    const float* conv_b = (const float*)d_in[3];
    const float* xp_w   = (const float*)d_in[4];
    const float* dt_w   = (const float*)d_in[5];
    const float* dt_b   = (const float*)d_in[6];
    const float* A_log  = (const float*)d_in[7];
    const float* D_par  = (const float*)d_in[8];
    const float* out_w  = (const float*)d_in[9];

    float *xz, *yg, *zb;
    cudaGetSymbolAddress((void**)&xz, g_xz);
    cudaGetSymbolAddress((void**)&yg, g_yg);
    cudaGetSymbolAddress((void**)&zb, g_z);

    cudaFuncSetAttribute(gemm_tc, cudaFuncAttributeMaxDynamicSharedMemorySize,
                         GEMM_SMEM);

    const dim3 scan_grid(PCHUNK, DINNER / 4, BATCH);
    const float* zin = z;
    for (int l = 0; l < 2; l++) {
        float* zout = (l == 0) ? zb : (float*)d_out;
        // in_proj: [8192,256] @ [1024,256]^T -> [8192,1024]
        gemm_tc<<<dim3(1024 / 128, ROWS / 128), 256, GEMM_SMEM>>>(
            zin, in_w + (size_t)l * 1024 * DMODEL, xz, 1024, DMODEL);
        conv_silu_k<<<(ROWS * DINNER) / 256, 256>>>(
            conv_w + (size_t)l * DINNER * 4, conv_b + (size_t)l * DINNER);
        xproj_k<<<ROWS / 64, 192>>>(xp_w + (size_t)l * XDBL_N * DINNER);
        dtproj_k<<<ROWS / 16, 512>>>(
            dt_w + (size_t)l * DINNER * DTRANK, dt_b + (size_t)l * DINNER);
        scan_pass1<<<scan_grid, 64>>>(A_log + (size_t)l * DINNER * DSTATE);
        scan_fixup<<<(BATCH * DINNER * DSTATE) / 256, 256>>>();
        scan_pass2<<<scan_grid, 64>>>(
            A_log + (size_t)l * DINNER * DSTATE, D_par + (size_t)l * DINNER);
        // out_proj: [8192,512] @ [256,512]^T -> [8192,256]
        gemm_tc<<<dim3(DMODEL / 128, ROWS / 128), 256, GEMM_SMEM>>>(
            yg, out_w + (size_t)l * DMODEL * DINNER, zout, DMODEL, DINNER);
        zin = zout;
    }
}

// round 4
// speedup vs baseline: 1.6787x; 1.2611x over previous
#include <cuda_runtime.h>
#include <cuda_bf16.h>
#include <cstdint>

// ---------------------------------------------------------------------------
// StateTransitionModel (2-layer Mamba), round 4:
//   bf16 2-term-split (3xMMA m16n8k16) tensor GEMMs for in/x/out projections,
//   register-weight dtproj + fast softplus, 16-channel scan blocks.
// ---------------------------------------------------------------------------

#define LOG2E  1.4426950408889634f
#define LN2    0.6931471805599453f

static const int BATCH   = 2;
static const int SEQ     = 4096;
static const int ROWS    = BATCH * SEQ;   // 8192
static const int DMODEL  = 256;
static const int DINNER  = 512;
static const int DSTATE  = 16;
static const int XDBL_P  = 64;            // padded x_dbl row stride (dt|B|C|pad)
static const int PCHUNK  = 8;
static const int CLEN    = SEQ / PCHUNK;  // 512

// scratch (device globals; no runtime allocation allowed)
__device__ float g_xz  [ROWS * 2 * DINNER];
__device__ float g_xs  [ROWS * DINNER];
__device__ float g_gs  [ROWS * DINNER];
__device__ float g_xdbl[ROWS * XDBL_P];
__device__ float g_dt  [ROWS * DINNER];
__device__ float g_yg  [ROWS * DINNER];
__device__ float g_z   [ROWS * DMODEL];
__device__ float g_hf  [BATCH * PCHUNK * DINNER * DSTATE];
__device__ float g_dec [BATCH * PCHUNK * DINNER * DSTATE];
__device__ float g_hi  [BATCH * PCHUNK * DINNER * DSTATE];

// ---------------------------------------------------------------- intrinsics
__device__ __forceinline__ float ex2f(float x) {
    float y; asm("ex2.approx.f32 %0, %1;" : "=f"(y) : "f"(x)); return y;
}
__device__ __forceinline__ float lg2f(float x) {
    float y; asm("lg2.approx.f32 %0, %1;" : "=f"(y) : "f"(x)); return y;
}
__device__ __forceinline__ float rcpf(float x) {
    float y; asm("rcp.approx.f32 %0, %1;" : "=f"(y) : "f"(x)); return y;
}
__device__ __forceinline__ void cp16(void* dst, const void* src) {
    unsigned d = (unsigned)__cvta_generic_to_shared(dst);
    asm volatile("cp.async.ca.shared.global [%0], [%1], 16;" :: "r"(d), "l"(src));
}
__device__ __forceinline__ void mma_bf16(float* c, uint32_t a0, uint32_t a1,
                                         uint32_t a2, uint32_t a3,
                                         uint32_t b0, uint32_t b1) {
    asm volatile(
        "mma.sync.aligned.m16n8k16.row.col.f32.bf16.bf16.f32 "
        "{%0,%1,%2,%3}, {%4,%5,%6,%7}, {%8,%9}, {%0,%1,%2,%3};"
        : "+f"(c[0]), "+f"(c[1]), "+f"(c[2]), "+f"(c[3])
        : "r"(a0), "r"(a1), "r"(a2), "r"(a3), "r"(b0), "r"(b1));
}
// split float4 into bf16x2 hi pair + bf16x2 lo (residual) pair
__device__ __forceinline__ void split4(float4 v, uint32_t& h0, uint32_t& h1,
                                       uint32_t& l0, uint32_t& l1) {
    __nv_bfloat162 a = __floats2bfloat162_rn(v.x, v.y);
    __nv_bfloat162 b = __floats2bfloat162_rn(v.z, v.w);
    float rx = v.x - __bfloat162float(a.x);
    float ry = v.y - __bfloat162float(a.y);
    float rz = v.z - __bfloat162float(b.x);
    float rw = v.w - __bfloat162float(b.y);
    __nv_bfloat162 c = __floats2bfloat162_rn(rx, ry);
    __nv_bfloat162 d = __floats2bfloat162_rn(rz, rw);
    h0 = *(uint32_t*)&a; h1 = *(uint32_t*)&b;
    l0 = *(uint32_t*)&c; l1 = *(uint32_t*)&d;
}

// ----------------------------------------------------- bf16-split GEMM (NT)
// C[M,N] = A[M,K] @ W[N,K]^T, fp32 in/out, 3x mma m16n8k16 bf16 (2-term split).
// CTA tile 128 x NT, warp tile 64x32, K-chunk 32 floats (16 b32 pairs),
// smem stride 20 b32 (conflict-free fragment loads), double-buffered.
static const int KB32 = 16;      // b32 words per row per chunk
static const int KSTR = 20;      // padded row stride (b32)

template<int NT, int THREADS>
__global__ void __launch_bounds__(THREADS) gemm_bf16(
    const float* __restrict__ A, const float* __restrict__ W,
    float* __restrict__ C, int N, int K, int Nw)
{
    extern __shared__ uint32_t sm[];
    uint32_t* sAh = sm;                        // 2 x 128 x 20
    uint32_t* sAl = sm + 2 * 128 * KSTR;
    uint32_t* sWh = sm + 4 * 128 * KSTR;       // 2 x NT x 20
    uint32_t* sWl = sWh + 2 * NT * KSTR;

    const int tid  = threadIdx.x;
    const int bm   = blockIdx.y << 7;
    const int bn   = blockIdx.x * NT;
    const int warp = tid >> 5, lane = tid & 31;
    const int WN   = NT / 32;
    const int wm   = warp / WN, wn = warp % WN;
    const int gid  = lane >> 2, tig = lane & 3;

    constexpr int A_IT = (128 * 32 / 4) / THREADS;
    constexpr int W_IT = (NT  * 32 / 4) / THREADS;

    float acc[4][4][4];
#pragma unroll
    for (int i = 0; i < 4; i++)
#pragma unroll
        for (int j = 0; j < 4; j++)
#pragma unroll
            for (int q = 0; q < 4; q++) acc[i][j][q] = 0.f;

    float4 ra[A_IT], rw[W_IT];

    auto ldg = [&](int c) {
        const int kc = c << 5;
#pragma unroll
        for (int r = 0; r < A_IT; r++) {
            int idx = tid + r * THREADS;
            int row = idx >> 3, q = (idx & 7) << 2;
            ra[r] = *(const float4*)(A + (size_t)(bm + row) * K + kc + q);
        }
#pragma unroll
        for (int r = 0; r < W_IT; r++) {
            int idx = tid + r * THREADS;
            int row = idx >> 3, q = (idx & 7) << 2;
            rw[r] = (row < Nw)
                ? *(const float4*)(W + (size_t)(bn + row) * K + kc + q)
                : make_float4(0.f, 0.f, 0.f, 0.f);
        }
    };
    auto sts = [&](int buf) {
        const int ao = buf * 128 * KSTR, wo = buf * NT * KSTR;
#pragma unroll
        for (int r = 0; r < A_IT; r++) {
            int idx = tid + r * THREADS;
            int row = idx >> 3, c2 = (idx & 7) << 1;
            uint32_t h0, h1, l0, l1;
            split4(ra[r], h0, h1, l0, l1);
            *(uint2*)(sAh + ao + row * KSTR + c2) = make_uint2(h0, h1);
            *(uint2*)(sAl + ao + row * KSTR + c2) = make_uint2(l0, l1);
        }
#pragma unroll
        for (int r = 0; r < W_IT; r++) {
            int idx = tid + r * THREADS;
            int row = idx >> 3, c2 = (idx & 7) << 1;
            uint32_t h0, h1, l0, l1;
            split4(rw[r], h0, h1, l0, l1);
            *(uint2*)(sWh + wo + row * KSTR + c2) = make_uint2(h0, h1);
            *(uint2*)(sWl + wo + row * KSTR + c2) = make_uint2(l0, l1);
        }
    };
    auto compute = [&](int buf) {
        const uint32_t* Ah = sAh + buf * 128 * KSTR;
        const uint32_t* Al = sAl + buf * 128 * KSTR;
        const uint32_t* Wh = sWh + buf * NT * KSTR;
        const uint32_t* Wl = sWl + buf * NT * KSTR;
#pragma unroll
        for (int j = 0; j < 2; j++) {
            const int k0 = (j << 3) + tig;
            uint32_t ah[4][4], al[4][4], bh[4][2], bl[4][2];
#pragma unroll
            for (int mi = 0; mi < 4; mi++) {
                int m = (wm << 6) + (mi << 4) + gid;
                ah[mi][0] = Ah[m * KSTR + k0];
                ah[mi][1] = Ah[(m + 8) * KSTR + k0];
                ah[mi][2] = Ah[m * KSTR + k0 + 4];
                ah[mi][3] = Ah[(m + 8) * KSTR + k0 + 4];
                al[mi][0] = Al[m * KSTR + k0];
                al[mi][1] = Al[(m + 8) * KSTR + k0];
                al[mi][2] = Al[m * KSTR + k0 + 4];
                al[mi][3] = Al[(m + 8) * KSTR + k0 + 4];
            }
#pragma unroll
            for (int nj = 0; nj < 4; nj++) {
                int n = (wn << 5) + (nj << 3) + gid;
                bh[nj][0] = Wh[n * KSTR + k0];
                bh[nj][1] = Wh[n * KSTR + k0 + 4];
                bl[nj][0] = Wl[n * KSTR + k0];
                bl[nj][1] = Wl[n * KSTR + k0 + 4];
            }
#pragma unroll
            for (int mi = 0; mi < 4; mi++)
#pragma unroll
                for (int nj = 0; nj < 4; nj++) {
                    mma_bf16(acc[mi][nj], ah[mi][0], ah[mi][1], ah[mi][2], ah[mi][3],
                             bh[nj][0], bh[nj][1]);
                    mma_bf16(acc[mi][nj], al[mi][0], al[mi][1], al[mi][2], al[mi][3],
                             bh[nj][0], bh[nj][1]);
                    mma_bf16(acc[mi][nj], ah[mi][0], ah[mi][1], ah[mi][2], ah[mi][3],
                             bl[nj][0], bl[nj][1]);
                }
        }
    };

    const int NC = K >> 5;
    ldg(0); sts(0); __syncthreads();
    for (int c = 0; c < NC; c++) {
        if (c + 1 < NC) ldg(c + 1);
        compute(c & 1);
        if (c + 1 < NC) { sts((c + 1) & 1); __syncthreads(); }
    }

#pragma unroll
    for (int mi = 0; mi < 4; mi++)
#pragma unroll
        for (int nj = 0; nj < 4; nj++) {
            int row = bm + (wm << 6) + (mi << 4) + gid;
            int col = bn + (wn << 5) + (nj << 3) + (tig << 1);
            *(float2*)(C + (size_t)row * N + col) =
                make_float2(acc[mi][nj][0], acc[mi][nj][1]);
            *(float2*)(C + (size_t)(row + 8) * N + col) =
                make_float2(acc[mi][nj][2], acc[mi][nj][3]);
        }
}

static const int GSM128 = (4 * 128 * KSTR + 4 * 128 * KSTR) * 4;   // 81920
static const int GSM64  = (4 * 128 * KSTR + 4 * 64  * KSTR) * 4;   // 61440

// --------------------------------------- causal depthwise conv + both silus
__global__ void __launch_bounds__(256) conv_silu_k(
    const float* __restrict__ cw, const float* __restrict__ cb)
{
    int idx = blockIdx.x * 256 + threadIdx.x;
    int d = idx & (DINNER - 1);
    int row = idx >> 9;
    int t = row & (SEQ - 1);
    float4 w = *(const float4*)(cw + (d << 2));
    float acc = cb[d];
    if (t >= 3) acc += g_xz[(size_t)(row - 3) * 1024 + d] * w.x;
    if (t >= 2) acc += g_xz[(size_t)(row - 2) * 1024 + d] * w.y;
    if (t >= 1) acc += g_xz[(size_t)(row - 1) * 1024 + d] * w.z;
    acc += g_xz[(size_t)row * 1024 + d] * w.w;
    g_xs[idx] = acc * rcpf(1.f + ex2f(-acc * LOG2E));
    float g = g_xz[(size_t)row * 1024 + DINNER + d];
    g_gs[idx] = g * rcpf(1.f + ex2f(-g * LOG2E));
}

// ------------------------------------------------- dt_proj + softplus (K=16)
// 128 blocks x 512 thr; thread = one d-channel, weights in registers,
// 64 rows per block staged via smem; fast softplus (ex2/lg2).
__global__ void __launch_bounds__(512) dtproj_k(
    const float* __restrict__ dtw, const float* __restrict__ dtb)
{
    __shared__ float din[64][17];
    const int tid = threadIdx.x;
    const int row0 = blockIdx.x << 6;

    float w[16];
    {
        const float4* wp = (const float4*)(dtw + tid * 16);
#pragma unroll
        for (int i = 0; i < 4; i++) {
            float4 v = wp[i];
            w[i * 4 + 0] = v.x; w[i * 4 + 1] = v.y;
            w[i * 4 + 2] = v.z; w[i * 4 + 3] = v.w;
        }
    }
    for (int idx = tid; idx < 64 * 16; idx += 512) {
        int r = idx >> 4, k = idx & 15;
        din[r][k] = g_xdbl[(size_t)(row0 + r) * XDBL_P + k];
    }
    float bias = dtb[tid];
    __syncthreads();

#pragma unroll 4
    for (int r = 0; r < 64; r++) {
        float acc = bias;
#pragma unroll
        for (int k = 0; k < 16; k++) acc += din[r][k] * w[k];
        float sp = (acc > 20.f) ? acc
                                : lg2f(1.f + ex2f(acc * LOG2E)) * LN2;
        g_dt[(size_t)(row0 + r) * DINNER + tid] = sp;
    }
}

// ------------------------------------------------ scan pass1: local chunks
// grid (PCHUNK, DINNER/16, BATCH), 256 thr = 16 d-channels x 16 states.
#define SCHUNK 64
__global__ void __launch_bounds__(256) scan_pass1(const float* __restrict__ A_log)
{
    __shared__ float s_dt[2][SCHUNK][16];
    __shared__ float s_x [2][SCHUNK][16];
    __shared__ float s_b [2][SCHUNK][16];

    const int tid = threadIdx.x;
    const int chunk = blockIdx.x, dblk = blockIdx.y, b = blockIdx.z;
    const int d0 = dblk << 4;
    const int p = tid >> 4, n = tid & 15;
    const int d = d0 + p;

    const float A2 = -__expf(A_log[d * DSTATE + n]) * LOG2E;
    float h = 0.f, sumdt = 0.f;
    const long base = (long)b * SEQ + (long)chunk * CLEN;
    const int lrow = tid >> 2, lq = (tid & 3) << 2;

    auto load = [&](int cc, int buf) {
        long tb = base + (long)cc * SCHUNK;
        cp16(&s_dt[buf][lrow][lq], &g_dt  [(tb + lrow) * DINNER + d0 + lq]);
        cp16(&s_x [buf][lrow][lq], &g_xs  [(tb + lrow) * DINNER + d0 + lq]);
        cp16(&s_b [buf][lrow][lq], &g_xdbl[(tb + lrow) * XDBL_P + 16 + lq]);
    };

    load(0, 0); asm volatile("cp.async.commit_group;");
    load(1, 1); asm volatile("cp.async.commit_group;");

    for (int cc = 0; cc < CLEN / SCHUNK; cc++) {
        const int buf = cc & 1;
        asm volatile("cp.async.wait_group 1;");
        __syncthreads();
#pragma unroll 8
        for (int i = 0; i < SCHUNK; i++) {
            float dtv = s_dt[buf][i][p];
            float xv  = s_x [buf][i][p];
            float Bv  = s_b [buf][i][n];
            h = ex2f(dtv * A2) * h + (dtv * xv) * Bv;
            sumdt += dtv;
        }
        __syncthreads();
        if (cc + 2 < CLEN / SCHUNK) load(cc + 2, buf);
        asm volatile("cp.async.commit_group;");
    }
    int o = ((b * PCHUNK + chunk) * DINNER + d) * DSTATE + n;
    g_hf [o] = h;
    g_dec[o] = ex2f(A2 * sumdt);
}

// --------------------------------------- scan fixup: sequential over chunks
__global__ void __launch_bounds__(256) scan_fixup()
{
    int idx = blockIdx.x * 256 + threadIdx.x;
    int b = idx >> 13;
    int dn = idx & 8191;
    float h = 0.f;
#pragma unroll
    for (int c = 0; c < PCHUNK; c++) {
        int o = ((b * PCHUNK + c) << 13) + dn;
        g_hi[o] = h;
        h = g_hf[o] + g_dec[o] * h;
    }
}

// -------------------------------- scan pass2: corrected scan + y + gate mul
__global__ void __launch_bounds__(256) scan_pass2(
    const float* __restrict__ A_log, const float* __restrict__ Dpar)
{
    __shared__ float s_dt[2][SCHUNK][16];
    __shared__ float s_x [2][SCHUNK][16];
    __shared__ float s_g [2][SCHUNK][16];
    __shared__ float s_b [2][SCHUNK][16];
    __shared__ float s_c [2][SCHUNK][16];
    __shared__ float s_y [SCHUNK][16];

    const int tid = threadIdx.x;
    const int chunk = blockIdx.x, dblk = blockIdx.y, b = blockIdx.z;
    const int d0 = dblk << 4;
    const int p = tid >> 4, n = tid & 15;
    const int d = d0 + p;

    const float A2 = -__expf(A_log[d * DSTATE + n]) * LOG2E;
    const float Dp = Dpar[d];
    float h = g_hi[((b * PCHUNK + chunk) * DINNER + d) * DSTATE + n];
    const long base = (long)b * SEQ + (long)chunk * CLEN;
    const int lrow = tid >> 2, lq = (tid & 3) << 2;

    auto load = [&](int cc, int buf) {
        long tb = base + (long)cc * SCHUNK;
        cp16(&s_dt[buf][lrow][lq], &g_dt  [(tb + lrow) * DINNER + d0 + lq]);
        cp16(&s_x [buf][lrow][lq], &g_xs  [(tb + lrow) * DINNER + d0 + lq]);
        cp16(&s_g [buf][lrow][lq], &g_gs  [(tb + lrow) * DINNER + d0 + lq]);
        cp16(&s_b [buf][lrow][lq], &g_xdbl[(tb + lrow) * XDBL_P + 16 + lq]);
        cp16(&s_c [buf][lrow][lq], &g_xdbl[(tb + lrow) * XDBL_P + 32 + lq]);
    };

    load(0, 0); asm volatile("cp.async.commit_group;");
    load(1, 1); asm volatile("cp.async.commit_group;");

    for (int cc = 0; cc < CLEN / SCHUNK; cc++) {
        const int buf = cc & 1;
        asm volatile("cp.async.wait_group 1;");
        __syncthreads();
        const long outb = base + (long)cc * SCHUNK;
#pragma unroll 8
        for (int i = 0; i < SCHUNK; i++) {
            float dtv = s_dt[buf][i][p];
            float xv  = s_x [buf][i][p];
            float Bv  = s_b [buf][i][n];
            float Cv  = s_c [buf][i][n];
            h = ex2f(dtv * A2) * h + (dtv * xv) * Bv;
            float r = h * Cv;
            r += __shfl_xor_sync(0xffffffffu, r, 8);
            r += __shfl_xor_sync(0xffffffffu, r, 4);
            r += __shfl_xor_sync(0xffffffffu, r, 2);
            r += __shfl_xor_sync(0xffffffffu, r, 1);
            if (n == 0)
                s_y[i][p] = (r + xv * Dp) * s_g[buf][i][p];
        }
        __syncthreads();
        // coalesced y tile store
        *(float4*)(&g_yg[(outb + lrow) * DINNER + d0 + lq]) =
            *(float4*)(&s_y[lrow][lq]);
        if (cc + 2 < CLEN / SCHUNK) load(cc + 2, buf);
        asm volatile("cp.async.commit_group;");
    }
}

// ------------------------------------------------------------------- launch
extern "C" void kernel_launch(void* const* d_in, const int* in_sizes, int n_in,
                              void* d_out, int out_size)
{
    const float* z      = (const float*)d_in[0];
    const float* in_w   = (const float*)d_in[1];
    const float* conv_w = (const float*)d_in[2];
    const float* conv_b = (const float*)d_in[3];
    const float* xp_w   = (const float*)d_in[4];
    const float* dt_w   = (const float*)d_in[5];
    const float* dt_b   = (const float*)d_in[6];
    const float* A_log  = (const float*)d_in[7];
    const float* D_par  = (const float*)d_in[8];
    const float* out_w  = (const float*)d_in[9];

    float *xz, *xs, *xdbl, *yg, *zb;
    cudaGetSymbolAddress((void**)&xz,   g_xz);
    cudaGetSymbolAddress((void**)&xs,   g_xs);
    cudaGetSymbolAddress((void**)&xdbl, g_xdbl);
    cudaGetSymbolAddress((void**)&yg,   g_yg);
    cudaGetSymbolAddress((void**)&zb,   g_z);

    cudaFuncSetAttribute((const void*)gemm_bf16<128, 256>,
                         cudaFuncAttributeMaxDynamicSharedMemorySize, GSM128);
    cudaFuncSetAttribute((const void*)gemm_bf16<64, 128>,
                         cudaFuncAttributeMaxDynamicSharedMemorySize, GSM64);

    const dim3 scan_grid(PCHUNK, DINNER / 16, BATCH);
    const float* zin = z;
    for (int l = 0; l < 2; l++) {
        float* zout = (l == 0) ? zb : (float*)d_out;
        // in_proj: [8192,256] @ [1024,256]^T -> [8192,1024]
        gemm_bf16<128, 256><<<dim3(8, 64), 256, GSM128>>>(
            zin, in_w + (size_t)l * 1024 * DMODEL, xz, 1024, DMODEL, 1024);
        conv_silu_k<<<(ROWS * DINNER) / 256, 256>>>(
            conv_w + (size_t)l * DINNER * 4, conv_b + (size_t)l * DINNER);
        // x_proj: [8192,512] @ [48,512]^T -> [8192,64-padded]
        gemm_bf16<64, 128><<<dim3(1, 64), 128, GSM64>>>(
            xs, xp_w + (size_t)l * 48 * DINNER, xdbl, XDBL_P, DINNER, 48);
        dtproj_k<<<ROWS / 64, 512>>>(
            dt_w + (size_t)l * DINNER * 16, dt_b + (size_t)l * DINNER);
        scan_pass1<<<scan_grid, 256>>>(A_log + (size_t)l * DINNER * DSTATE);
        scan_fixup<<<(BATCH * DINNER * DSTATE) / 256, 256>>>();
        scan_pass2<<<scan_grid, 256>>>(
            A_log + (size_t)l * DINNER * DSTATE, D_par + (size_t)l * DINNER);
        // out_proj: [8192,512] @ [256,512]^T -> [8192,256]
        gemm_bf16<128, 256><<<dim3(2, 64), 256, GSM128>>>(
            yg, out_w + (size_t)l * DMODEL * DINNER, zout, DMODEL, DINNER, 256);
        zin = zout;
    }
}

// round 5
// speedup vs baseline: 1.7410x; 1.0371x over previous
#include <cuda_runtime.h>
#include <cuda_bf16.h>
#include <cstdint>

// ---------------------------------------------------------------------------
// StateTransitionModel (2-layer Mamba), round 5:
//   ldmatrix-fed bf16-split GEMMs, wave-filled dtproj, fixup fused into pass2,
//   vectorized conv.
// ---------------------------------------------------------------------------

#define LOG2E  1.4426950408889634f
#define LN2    0.6931471805599453f

static const int BATCH   = 2;
static const int SEQ     = 4096;
static const int ROWS    = BATCH * SEQ;   // 8192
static const int DMODEL  = 256;
static const int DINNER  = 512;
static const int DSTATE  = 16;
static const int XDBL_P  = 64;            // padded x_dbl row stride (dt|B|C|pad)
static const int PCHUNK  = 8;
static const int CLEN    = SEQ / PCHUNK;  // 512

// scratch (device globals; no runtime allocation allowed)
__device__ float g_xz  [ROWS * 2 * DINNER];
__device__ float g_xs  [ROWS * DINNER];
__device__ float g_gs  [ROWS * DINNER];
__device__ float g_xdbl[ROWS * XDBL_P];
__device__ float g_dt  [ROWS * DINNER];
__device__ float g_yg  [ROWS * DINNER];
__device__ float g_z   [ROWS * DMODEL];
__device__ float g_hf  [BATCH * PCHUNK * DINNER * DSTATE];
__device__ float g_dec [BATCH * PCHUNK * DINNER * DSTATE];

// ---------------------------------------------------------------- intrinsics
__device__ __forceinline__ float ex2f(float x) {
    float y; asm("ex2.approx.f32 %0, %1;" : "=f"(y) : "f"(x)); return y;
}
__device__ __forceinline__ float lg2f(float x) {
    float y; asm("lg2.approx.f32 %0, %1;" : "=f"(y) : "f"(x)); return y;
}
__device__ __forceinline__ float rcpf(float x) {
    float y; asm("rcp.approx.f32 %0, %1;" : "=f"(y) : "f"(x)); return y;
}
__device__ __forceinline__ float siluf(float x) {
    return x * rcpf(1.f + ex2f(-x * LOG2E));
}
__device__ __forceinline__ void cp16(void* dst, const void* src) {
    unsigned d = (unsigned)__cvta_generic_to_shared(dst);
    asm volatile("cp.async.ca.shared.global [%0], [%1], 16;" :: "r"(d), "l"(src));
}
__device__ __forceinline__ void mma_bf16(float* c, const uint32_t* a,
                                         const uint32_t* b) {
    asm volatile(
        "mma.sync.aligned.m16n8k16.row.col.f32.bf16.bf16.f32 "
        "{%0,%1,%2,%3}, {%4,%5,%6,%7}, {%8,%9}, {%0,%1,%2,%3};"
        : "+f"(c[0]), "+f"(c[1]), "+f"(c[2]), "+f"(c[3])
        : "r"(a[0]), "r"(a[1]), "r"(a[2]), "r"(a[3]), "r"(b[0]), "r"(b[1]));
}
__device__ __forceinline__ void ldm_x4(uint32_t* r, uint32_t addr) {
    asm volatile(
        "ldmatrix.sync.aligned.m8n8.x4.shared.b16 {%0,%1,%2,%3}, [%4];"
        : "=r"(r[0]), "=r"(r[1]), "=r"(r[2]), "=r"(r[3]) : "r"(addr));
}
// split float4 into bf16x2 hi pair + bf16x2 lo (residual) pair
__device__ __forceinline__ void split4(float4 v, uint32_t& h0, uint32_t& h1,
                                       uint32_t& l0, uint32_t& l1) {
    __nv_bfloat162 a = __floats2bfloat162_rn(v.x, v.y);
    __nv_bfloat162 b = __floats2bfloat162_rn(v.z, v.w);
    float rx = v.x - __bfloat162float(a.x);
    float ry = v.y - __bfloat162float(a.y);
    float rz = v.z - __bfloat162float(b.x);
    float rw = v.w - __bfloat162float(b.y);
    __nv_bfloat162 c = __floats2bfloat162_rn(rx, ry);
    __nv_bfloat162 d = __floats2bfloat162_rn(rz, rw);
    h0 = *(uint32_t*)&a; h1 = *(uint32_t*)&b;
    l0 = *(uint32_t*)&c; l1 = *(uint32_t*)&d;
}

// ----------------------------------------------------- bf16-split GEMM (NT)
// C[M,N] = A[M,K] @ W[N,K]^T, fp32 in/out, 3x mma m16n8k16 bf16 (2-term split).
// CTA tile 128 x NT, warp tile 64x32, K-chunk 32 floats, smem stride 20 b32
// (conflict-free for both STS and ldmatrix), double-buffered, ldmatrix-fed.
static const int KSTR = 20;      // padded row stride (b32)

template<int NT, int THREADS>
__global__ void __launch_bounds__(THREADS) gemm_bf16(
    const float* __restrict__ A, const float* __restrict__ W,
    float* __restrict__ C, int N, int K, int Nw)
{
    extern __shared__ uint32_t sm[];
    const int AH = 0;
    const int AL = 2 * 128 * KSTR;
    const int WH = 4 * 128 * KSTR;
    const int WL = WH + 2 * NT * KSTR;

    uint32_t sbase;
    asm("{ .reg .u64 t; cvta.to.shared.u64 t, %1; cvt.u32.u64 %0, t; }"
        : "=r"(sbase) : "l"(sm));

    const int tid  = threadIdx.x;
    const int bm   = blockIdx.y << 7;
    const int bn   = blockIdx.x * NT;
    const int warp = tid >> 5, lane = tid & 31;
    const int WN   = NT / 32;
    const int wm   = warp / WN, wn = warp % WN;
    const int gid  = lane >> 2, tig = lane & 3;

    // ldmatrix lane address components
    const int q = lane >> 3, rr = lane & 7;
    const int a_row = (q & 1) * 8 + rr, a_word = (q >> 1) * 4;
    const int b_row = (q >> 1) * 8 + rr, b_word = (q & 1) * 4;

    constexpr int A_IT = (128 * 32 / 4) / THREADS;
    constexpr int W_IT = (NT  * 32 / 4) / THREADS;

    float acc[4][4][4];
#pragma unroll
    for (int i = 0; i < 4; i++)
#pragma unroll
        for (int j = 0; j < 4; j++)
#pragma unroll
            for (int qq = 0; qq < 4; qq++) acc[i][j][qq] = 0.f;

    float4 ra[A_IT], rw[W_IT];

    auto ldg = [&](int c) {
        const int kc = c << 5;
#pragma unroll
        for (int r = 0; r < A_IT; r++) {
            int idx = tid + r * THREADS;
            int row = idx >> 3, qo = (idx & 7) << 2;
            ra[r] = *(const float4*)(A + (size_t)(bm + row) * K + kc + qo);
        }
#pragma unroll
        for (int r = 0; r < W_IT; r++) {
            int idx = tid + r * THREADS;
            int row = idx >> 3, qo = (idx & 7) << 2;
            rw[r] = (row < Nw)
                ? *(const float4*)(W + (size_t)(bn + row) * K + kc + qo)
                : make_float4(0.f, 0.f, 0.f, 0.f);
        }
    };
    auto sts = [&](int buf) {
        const int ao = AH + buf * 128 * KSTR, alo = AL + buf * 128 * KSTR;
        const int wo = WH + buf * NT * KSTR,  wlo = WL + buf * NT * KSTR;
#pragma unroll
        for (int r = 0; r < A_IT; r++) {
            int idx = tid + r * THREADS;
            int row = idx >> 3, c2 = (idx & 7) << 1;
            uint32_t h0, h1, l0, l1;
            split4(ra[r], h0, h1, l0, l1);
            *(uint2*)(sm + ao  + row * KSTR + c2) = make_uint2(h0, h1);
            *(uint2*)(sm + alo + row * KSTR + c2) = make_uint2(l0, l1);
        }
#pragma unroll
        for (int r = 0; r < W_IT; r++) {
            int idx = tid + r * THREADS;
            int row = idx >> 3, c2 = (idx & 7) << 1;
            uint32_t h0, h1, l0, l1;
            split4(rw[r], h0, h1, l0, l1);
            *(uint2*)(sm + wo  + row * KSTR + c2) = make_uint2(h0, h1);
            *(uint2*)(sm + wlo + row * KSTR + c2) = make_uint2(l0, l1);
        }
    };
    auto compute = [&](int buf) {
        const uint32_t a_h = sbase + 4 * (AH + buf * 128 * KSTR +
                             ((wm << 6) + a_row) * KSTR + a_word);
        const uint32_t a_l = a_h + 4 * (AL - AH);
        const uint32_t w_h = sbase + 4 * (WH + buf * NT * KSTR +
                             ((wn << 5) + b_row) * KSTR + b_word);
        const uint32_t w_l = w_h + 4 * (WL - WH);
#pragma unroll
        for (int j = 0; j < 2; j++) {
            uint32_t ah[4][4], al[4][4], bh[4][2], bl[4][2];
#pragma unroll
            for (int mi = 0; mi < 4; mi++) {
                uint32_t off = 4 * ((mi << 4) * KSTR + (j << 3));
                ldm_x4(ah[mi], a_h + off);
                ldm_x4(al[mi], a_l + off);
            }
#pragma unroll
            for (int p = 0; p < 2; p++) {
                uint32_t off = 4 * ((p << 4) * KSTR + (j << 3));
                uint32_t t[4];
                ldm_x4(t, w_h + off);
                bh[2*p][0] = t[0]; bh[2*p][1] = t[1];
                bh[2*p+1][0] = t[2]; bh[2*p+1][1] = t[3];
                ldm_x4(t, w_l + off);
                bl[2*p][0] = t[0]; bl[2*p][1] = t[1];
                bl[2*p+1][0] = t[2]; bl[2*p+1][1] = t[3];
            }
#pragma unroll
            for (int mi = 0; mi < 4; mi++)
#pragma unroll
                for (int nj = 0; nj < 4; nj++) {
                    mma_bf16(acc[mi][nj], ah[mi], bh[nj]);
                    mma_bf16(acc[mi][nj], al[mi], bh[nj]);
                    mma_bf16(acc[mi][nj], ah[mi], bl[nj]);
                }
        }
    };

    const int NC = K >> 5;
    ldg(0); sts(0); __syncthreads();
    for (int c = 0; c < NC; c++) {
        if (c + 1 < NC) ldg(c + 1);
        compute(c & 1);
        if (c + 1 < NC) { sts((c + 1) & 1); __syncthreads(); }
    }

#pragma unroll
    for (int mi = 0; mi < 4; mi++)
#pragma unroll
        for (int nj = 0; nj < 4; nj++) {
            int row = bm + (wm << 6) + (mi << 4) + gid;
            int col = bn + (wn << 5) + (nj << 3) + (tig << 1);
            *(float2*)(C + (size_t)row * N + col) =
                make_float2(acc[mi][nj][0], acc[mi][nj][1]);
            *(float2*)(C + (size_t)(row + 8) * N + col) =
                make_float2(acc[mi][nj][2], acc[mi][nj][3]);
        }
}

static const int GSM128 = (4 * 128 * KSTR + 4 * 128 * KSTR) * 4;   // 81920
static const int GSM64  = (4 * 128 * KSTR + 4 * 64  * KSTR) * 4;   // 61440

// --------------------- causal depthwise conv + both silus (4 chan / thread)
__global__ void __launch_bounds__(256) conv_silu_k(
    const float* __restrict__ cw, const float* __restrict__ cb)
{
    int idx = blockIdx.x * 256 + threadIdx.x;   // over ROWS * DINNER/4
    int d4 = (idx & 127) << 2;
    int row = idx >> 7;
    int t = row & (SEQ - 1);

    float4 w0 = *(const float4*)(cw + ((d4 + 0) << 2));
    float4 w1 = *(const float4*)(cw + ((d4 + 1) << 2));
    float4 w2 = *(const float4*)(cw + ((d4 + 2) << 2));
    float4 w3 = *(const float4*)(cw + ((d4 + 3) << 2));
    float4 acc = *(const float4*)(cb + d4);

    if (t >= 3) {
        float4 v = *(const float4*)(&g_xz[(size_t)(row - 3) * 1024 + d4]);
        acc.x += v.x * w0.x; acc.y += v.y * w1.x;
        acc.z += v.z * w2.x; acc.w += v.w * w3.x;
    }
    if (t >= 2) {
        float4 v = *(const float4*)(&g_xz[(size_t)(row - 2) * 1024 + d4]);
        acc.x += v.x * w0.y; acc.y += v.y * w1.y;
        acc.z += v.z * w2.y; acc.w += v.w * w3.y;
    }
    if (t >= 1) {
        float4 v = *(const float4*)(&g_xz[(size_t)(row - 1) * 1024 + d4]);
        acc.x += v.x * w0.z; acc.y += v.y * w1.z;
        acc.z += v.z * w2.z; acc.w += v.w * w3.z;
    }
    {
        float4 v = *(const float4*)(&g_xz[(size_t)row * 1024 + d4]);
        acc.x += v.x * w0.w; acc.y += v.y * w1.w;
        acc.z += v.z * w2.w; acc.w += v.w * w3.w;
    }
    *(float4*)(&g_xs[(size_t)row * DINNER + d4]) =
        make_float4(siluf(acc.x), siluf(acc.y), siluf(acc.z), siluf(acc.w));

    float4 g = *(const float4*)(&g_xz[(size_t)row * 1024 + DINNER + d4]);
    *(float4*)(&g_gs[(size_t)row * DINNER + d4]) =
        make_float4(siluf(g.x), siluf(g.y), siluf(g.z), siluf(g.w));
}

// ------------------------------------------------- dt_proj + softplus (K=16)
// 256 blocks x 512 thr; thread = one d-channel, weights in registers,
// 32 rows per block; fast softplus (ex2/lg2).
__global__ void __launch_bounds__(512) dtproj_k(
    const float* __restrict__ dtw, const float* __restrict__ dtb)
{
    __shared__ float din[32][17];
    const int tid = threadIdx.x;
    const int row0 = blockIdx.x << 5;

    float w[16];
    {
        const float4* wp = (const float4*)(dtw + tid * 16);
#pragma unroll
        for (int i = 0; i < 4; i++) {
            float4 v = wp[i];
            w[i * 4 + 0] = v.x; w[i * 4 + 1] = v.y;
            w[i * 4 + 2] = v.z; w[i * 4 + 3] = v.w;
        }
    }
    if (tid < 32 * 16) {
        int r = tid >> 4, k = tid & 15;
        din[r][k] = g_xdbl[(size_t)(row0 + r) * XDBL_P + k];
    }
    float bias = dtb[tid];
    __syncthreads();

#pragma unroll 4
    for (int r = 0; r < 32; r++) {
        float acc = bias;
#pragma unroll
        for (int k = 0; k < 16; k++) acc += din[r][k] * w[k];
        float sp = (acc > 20.f) ? acc
                                : lg2f(1.f + ex2f(acc * LOG2E)) * LN2;
        g_dt[(size_t)(row0 + r) * DINNER + tid] = sp;
    }
}

// ------------------------------------------------ scan pass1: local chunks
// grid (PCHUNK, DINNER/16, BATCH), 256 thr = 16 d-channels x 16 states.
#define SCHUNK 64
__global__ void __launch_bounds__(256) scan_pass1(const float* __restrict__ A_log)
{
    __shared__ float s_dt[2][SCHUNK][16];
    __shared__ float s_x [2][SCHUNK][16];
    __shared__ float s_b [2][SCHUNK][16];

    const int tid = threadIdx.x;
    const int chunk = blockIdx.x, dblk = blockIdx.y, b = blockIdx.z;
    const int d0 = dblk << 4;
    const int p = tid >> 4, n = tid & 15;
    const int d = d0 + p;

    const float A2 = -__expf(A_log[d * DSTATE + n]) * LOG2E;
    float h = 0.f, sumdt = 0.f;
    const long base = (long)b * SEQ + (long)chunk * CLEN;
    const int lrow = tid >> 2, lq = (tid & 3) << 2;

    auto load = [&](int cc, int buf) {
        long tb = base + (long)cc * SCHUNK;
        cp16(&s_dt[buf][lrow][lq], &g_dt  [(tb + lrow) * DINNER + d0 + lq]);
        cp16(&s_x [buf][lrow][lq], &g_xs  [(tb + lrow) * DINNER + d0 + lq]);
        cp16(&s_b [buf][lrow][lq], &g_xdbl[(tb + lrow) * XDBL_P + 16 + lq]);
    };

    load(0, 0); asm volatile("cp.async.commit_group;");
    load(1, 1); asm volatile("cp.async.commit_group;");

    for (int cc = 0; cc < CLEN / SCHUNK; cc++) {
        const int buf = cc & 1;
        asm volatile("cp.async.wait_group 1;");
        __syncthreads();
#pragma unroll 8
        for (int i = 0; i < SCHUNK; i++) {
            float dtv = s_dt[buf][i][p];
            float xv  = s_x [buf][i][p];
            float Bv  = s_b [buf][i][n];
            h = ex2f(dtv * A2) * h + (dtv * xv) * Bv;
            sumdt += dtv;
        }
        __syncthreads();
        if (cc + 2 < CLEN / SCHUNK) load(cc + 2, buf);
        asm volatile("cp.async.commit_group;");
    }
    int o = ((b * PCHUNK + chunk) * DINNER + d) * DSTATE + n;
    g_hf [o] = h;
    g_dec[o] = ex2f(A2 * sumdt);
}

// ------------- scan pass2: inline fixup + corrected scan + y + gate mul
__global__ void __launch_bounds__(256) scan_pass2(
    const float* __restrict__ A_log, const float* __restrict__ Dpar)
{
    __shared__ float s_dt[2][SCHUNK][16];
    __shared__ float s_x [2][SCHUNK][16];
    __shared__ float s_g [2][SCHUNK][16];
    __shared__ float s_b [2][SCHUNK][16];
    __shared__ float s_c [2][SCHUNK][16];
    __shared__ float s_y [SCHUNK][16];

    const int tid = threadIdx.x;
    const int chunk = blockIdx.x, dblk = blockIdx.y, b = blockIdx.z;
    const int d0 = dblk << 4;
    const int p = tid >> 4, n = tid & 15;
    const int d = d0 + p;

    const float A2 = -__expf(A_log[d * DSTATE + n]) * LOG2E;
    const float Dp = Dpar[d];
    const long base = (long)b * SEQ + (long)chunk * CLEN;
    const int lrow = tid >> 2, lq = (tid & 3) << 2;

    auto load = [&](int cc, int buf) {
        long tb = base + (long)cc * SCHUNK;
        cp16(&s_dt[buf][lrow][lq], &g_dt  [(tb + lrow) * DINNER + d0 + lq]);
        cp16(&s_x [buf][lrow][lq], &g_xs  [(tb + lrow) * DINNER + d0 + lq]);
        cp16(&s_g [buf][lrow][lq], &g_gs  [(tb + lrow) * DINNER + d0 + lq]);
        cp16(&s_b [buf][lrow][lq], &g_xdbl[(tb + lrow) * XDBL_P + 16 + lq]);
        cp16(&s_c [buf][lrow][lq], &g_xdbl[(tb + lrow) * XDBL_P + 32 + lq]);
    };

    load(0, 0); asm volatile("cp.async.commit_group;");
    load(1, 1); asm volatile("cp.async.commit_group;");

    // inline fixup: fold all previous chunks' (hf, dec) into the initial state
    float h = 0.f;
    for (int c = 0; c < chunk; c++) {
        int o = ((b * PCHUNK + c) * DINNER + d) * DSTATE + n;
        h = g_hf[o] + g_dec[o] * h;
    }

    for (int cc = 0; cc < CLEN / SCHUNK; cc++) {
        const int buf = cc & 1;
        asm volatile("cp.async.wait_group 1;");
        __syncthreads();
        const long outb = base + (long)cc * SCHUNK;
#pragma unroll 8
        for (int i = 0; i < SCHUNK; i++) {
            float dtv = s_dt[buf][i][p];
            float xv  = s_x [buf][i][p];
            float Bv  = s_b [buf][i][n];
            float Cv  = s_c [buf][i][n];
            h = ex2f(dtv * A2) * h + (dtv * xv) * Bv;
            float r = h * Cv;
            r += __shfl_xor_sync(0xffffffffu, r, 8);
            r += __shfl_xor_sync(0xffffffffu, r, 4);
            r += __shfl_xor_sync(0xffffffffu, r, 2);
            r += __shfl_xor_sync(0xffffffffu, r, 1);
            if (n == 0)
                s_y[i][p] = (r + xv * Dp) * s_g[buf][i][p];
        }
        __syncthreads();
        *(float4*)(&g_yg[(outb + lrow) * DINNER + d0 + lq]) =
            *(float4*)(&s_y[lrow][lq]);
        if (cc + 2 < CLEN / SCHUNK) load(cc + 2, buf);
        asm volatile("cp.async.commit_group;");
    }
}

// ------------------------------------------------------------------- launch
extern "C" void kernel_launch(void* const* d_in, const int* in_sizes, int n_in,
                              void* d_out, int out_size)
{
    const float* z      = (const float*)d_in[0];
    const float* in_w   = (const float*)d_in[1];
    const float* conv_w = (const float*)d_in[2];
    const float* conv_b = (const float*)d_in[3];
    const float* xp_w   = (const float*)d_in[4];
    const float* dt_w   = (const float*)d_in[5];
    const float* dt_b   = (const float*)d_in[6];
    const float* A_log  = (const float*)d_in[7];
    const float* D_par  = (const float*)d_in[8];
    const float* out_w  = (const float*)d_in[9];

    float *xz, *xs, *xdbl, *yg, *zb;
    cudaGetSymbolAddress((void**)&xz,   g_xz);
    cudaGetSymbolAddress((void**)&xs,   g_xs);
    cudaGetSymbolAddress((void**)&xdbl, g_xdbl);
    cudaGetSymbolAddress((void**)&yg,   g_yg);
    cudaGetSymbolAddress((void**)&zb,   g_z);

    cudaFuncSetAttribute((const void*)gemm_bf16<128, 256>,
                         cudaFuncAttributeMaxDynamicSharedMemorySize, GSM128);
    cudaFuncSetAttribute((const void*)gemm_bf16<64, 128>,
                         cudaFuncAttributeMaxDynamicSharedMemorySize, GSM64);

    const dim3 scan_grid(PCHUNK, DINNER / 16, BATCH);
    const float* zin = z;
    for (int l = 0; l < 2; l++) {
        float* zout = (l == 0) ? zb : (float*)d_out;
        // in_proj: [8192,256] @ [1024,256]^T -> [8192,1024]
        gemm_bf16<128, 256><<<dim3(8, 64), 256, GSM128>>>(
            zin, in_w + (size_t)l * 1024 * DMODEL, xz, 1024, DMODEL, 1024);
        conv_silu_k<<<(ROWS * DINNER / 4) / 256, 256>>>(
            conv_w + (size_t)l * DINNER * 4, conv_b + (size_t)l * DINNER);
        // x_proj: [8192,512] @ [48,512]^T -> [8192,64-padded]
        gemm_bf16<64, 128><<<dim3(1, 64), 128, GSM64>>>(
            xs, xp_w + (size_t)l * 48 * DINNER, xdbl, XDBL_P, DINNER, 48);
        dtproj_k<<<ROWS / 32, 512>>>(
            dt_w + (size_t)l * DINNER * 16, dt_b + (size_t)l * DINNER);
        scan_pass1<<<scan_grid, 256>>>(A_log + (size_t)l * DINNER * DSTATE);
        scan_pass2<<<scan_grid, 256>>>(
            A_log + (size_t)l * DINNER * DSTATE, D_par + (size_t)l * DINNER);
        // out_proj: [8192,512] @ [256,512]^T -> [8192,256]
        gemm_bf16<128, 256><<<dim3(2, 64), 256, GSM128>>>(
            yg, out_w + (size_t)l * DMODEL * DINNER, zout, DMODEL, DINNER, 256);
        zin = zout;
    }
}